// round 9
// baseline (speedup 1.0000x reference)
#include <cuda_runtime.h>
#include <cuda_fp16.h>
#include <cstdint>

// Problem constants
constexpr int Nn = 50000;
constexpr int Ee = 800000;
constexpr int Ff = 128;
constexpr int Hh = 256;
constexpr int Cc = 64;

constexpr int SCAN_B = 512;
constexpr int NBLK = (Nn + SCAN_B - 1) / SCAN_B;  // 98

// Scratch
__device__ float g_hprime[(size_t)Nn * Ff];
__device__ float g_agg[(size_t)Nn * Ff];
__device__ float g_hh[(size_t)Nn * Hh];
__device__ float g_deg[Nn];     // dinv
__device__ float g_acc[8];
__device__ int g_cnt[Nn];
__device__ int g_fill[Nn];
__device__ int g_rowptr[Nn];    // block-local exclusive scan (+ g_bsum[i>>9])
__device__ int g_bsum[128];
__device__ int g_esrc[Ee];
__device__ int g_scnt;          // scan completion ticket

// ---------------------------------------------------------------------------
__global__ void init_k() {
    int i = blockIdx.x * blockDim.x + threadIdx.x;
    if (i < Nn) { g_cnt[i] = 0; g_fill[i] = 0; }
    if (i < 8) g_acc[i] = 0.0f;
    if (i == 0) g_scnt = 0;
}
__global__ void cnt_k(const int* __restrict__ adj) {
    int e = blockIdx.x * blockDim.x + threadIdx.x;
    if (e < Ee) atomicAdd(&g_cnt[adj[Ee + e]], 1);
}
// block scan + last-block converts g_bsum to exclusive prefix (fused scan2)
__global__ void scan1_k() {
    __shared__ int s[SCAN_B];
    __shared__ int slast;
    int tid = threadIdx.x;
    int i = blockIdx.x * SCAN_B + tid;
    int v = (i < Nn) ? g_cnt[i] : 0;
    s[tid] = v;
    __syncthreads();
#pragma unroll
    for (int off = 1; off < SCAN_B; off <<= 1) {
        int t = (tid >= off) ? s[tid - off] : 0;
        __syncthreads();
        s[tid] += t;
        __syncthreads();
    }
    if (i < Nn) {
        g_rowptr[i] = s[tid] - v;
        g_deg[i] = rsqrtf((float)(v + 1));
    }
    if (tid == SCAN_B - 1) g_bsum[blockIdx.x] = s[tid];
    __syncthreads();
    if (tid == 0) {
        __threadfence();
        slast = (atomicAdd(&g_scnt, 1) == NBLK - 1) ? 1 : 0;
    }
    __syncthreads();
    if (slast && tid < 128) {
        __shared__ int ws[4];
        volatile int* vb = (volatile int*)g_bsum;
        int bv = (tid < NBLK) ? vb[tid] : 0;
        int x = bv;
#pragma unroll
        for (int o = 1; o < 32; o <<= 1) {
            int t = __shfl_up_sync(0xffffffffu, x, o);
            if ((tid & 31) >= o) x += t;
        }
        if ((tid & 31) == 31) ws[tid >> 5] = x;
        __syncwarp();
        if (tid < 4) {  // tiny serial combine by thread 0 of warp 0
        }
        __syncthreads();
        if (tid == 0) {
            int run = 0;
#pragma unroll
            for (int w = 0; w < 4; w++) { int t = ws[w]; ws[w] = run; run += t; }
        }
        __syncthreads();
        if (tid < NBLK) g_bsum[tid] = x - bv + ws[tid >> 5];
    }
}
__global__ void fill_k(const int* __restrict__ adj) {
    int e = blockIdx.x * blockDim.x + threadIdx.x;
    if (e >= Ee) return;
    int src = adj[e];
    int dst = adj[Ee + e];
    int pos = g_rowptr[dst] + g_bsum[dst >> 9] + atomicAdd(&g_fill[dst], 1);
    g_esrc[pos] = src;
}

// ---------------------------------------------------------------------------
__device__ __forceinline__ uint32_t smem_u32(const void* p) {
    uint32_t a;
    asm("{ .reg .u64 t; cvta.to.shared.u64 t, %1; cvt.u32.u64 %0, t; }"
        : "=r"(a) : "l"(p));
    return a;
}
__device__ __forceinline__ void ldsm_x4(uint32_t* r, uint32_t addr) {
    asm volatile("ldmatrix.sync.aligned.m8n8.x4.shared.b16 {%0,%1,%2,%3}, [%4];"
                 : "=r"(r[0]), "=r"(r[1]), "=r"(r[2]), "=r"(r[3]) : "r"(addr));
}
__device__ __forceinline__ void ldsm_x2t(uint32_t* r, uint32_t addr) {
    asm volatile("ldmatrix.sync.aligned.m8n8.x2.trans.shared.b16 {%0,%1}, [%2];"
                 : "=r"(r[0]), "=r"(r[1]) : "r"(addr));
}
__device__ __forceinline__ void mma_f16(float* d, const uint32_t* a, const uint32_t* b) {
    asm volatile(
        "mma.sync.aligned.m16n8k16.row.col.f32.f16.f16.f32 "
        "{%0,%1,%2,%3}, {%4,%5,%6,%7}, {%8,%9}, {%0,%1,%2,%3};"
        : "+f"(d[0]), "+f"(d[1]), "+f"(d[2]), "+f"(d[3])
        : "r"(a[0]), "r"(a[1]), "r"(a[2]), "r"(a[3]), "r"(b[0]), "r"(b[1]));
}
__device__ __forceinline__ uint32_t pack_h2(__half a, __half b) {
    __half2 h = __halves2half2(a, b);
    return *(uint32_t*)&h;
}

// ---------------------------------------------------------------------------
// fp16 2-term HMMA GEMM, BK=64: C = A@B via Ah*(Bh+Bl).
// BM=128, BN=64, BK=64, 256 threads, 8 warps (4m x 2n), warp tile 32x32.
// AXF: 1 -> A'[r][k] = dinv[r]*A[r][k] + abias[k]
// EPI: 0 -> v*=dinv[r] -> C0 ; 1 -> relu(v+bias) -> C0 ; 3 -> v+bias -> 3 slices
template <int K, int AXF, int EPI>
__global__ void __launch_bounds__(256)
mmagemm(const float* __restrict__ A, const float* __restrict__ B,
        const float* __restrict__ abias, const float* __restrict__ bias,
        float* __restrict__ C0, int M, int Ncol) {
    constexpr int ASTR = 72;   // fp16 elems per A smem row (144B)
    constexpr int BSTR = 72;   // fp16 elems per B smem row (144B)
    __shared__ __align__(16) __half Ash[128 * ASTR];   // 18432 B
    __shared__ __align__(16) __half Bsh[64 * BSTR];    //  9216 B
    __shared__ __align__(16) __half Bsl[64 * BSTR];    //  9216 B

    const int tid = threadIdx.x;
    const int wid = tid >> 5;
    const int lane = tid & 31;
    const int wm = wid & 3;
    const int wn = wid >> 2;
    const int m0 = blockIdx.x * 128;
    const int n0 = blockIdx.y * 64;

    const uint32_t uAs = smem_u32(Ash);
    const uint32_t uBh = smem_u32(Bsh);
    const uint32_t uBl = smem_u32(Bsl);

    const int l15 = lane & 15;
    const int lh = lane >> 4;
    // A frag base (per mi), k-step adds ks*16 fp16 = 32B
    uint32_t aOff[2];
#pragma unroll
    for (int mi = 0; mi < 2; mi++)
        aOff[mi] = uAs + (uint32_t)(((wm * 32 + mi * 16 + l15) * ASTR + lh * 8) * 2);
    // B frag base: krow = ks*16 + l15, col = wn*32 + ni*8
    const uint32_t bOff = (uint32_t)((l15 * BSTR + wn * 32) * 2);

    float acc[2][4][4];
#pragma unroll
    for (int mi = 0; mi < 2; mi++)
#pragma unroll
        for (int ni = 0; ni < 4; ni++)
#pragma unroll
            for (int j = 0; j < 4; j++) acc[mi][ni][j] = 0.0f;

    constexpr int NC = K / 64;
#pragma unroll 1
    for (int c = 0; c < NC; c++) {
        const int k0 = c * 64;
        if (c > 0) __syncthreads();
        // ---- stage A (128 x 64 fp32 -> fp16): 8 float4/thread ----
#pragma unroll
        for (int it = 0; it < 8; it++) {
            int idx = it * 256 + tid;
            int r = idx >> 4, q = idx & 15;
            int gr = m0 + r;
            float4 v = make_float4(0.f, 0.f, 0.f, 0.f);
            if (gr < M) {
                v = *(const float4*)(A + (size_t)gr * K + k0 + q * 4);
                if (AXF) {
                    float sc = g_deg[gr];
                    float4 bb = *(const float4*)(abias + k0 + q * 4);
                    v.x = sc * v.x + bb.x; v.y = sc * v.y + bb.y;
                    v.z = sc * v.z + bb.z; v.w = sc * v.w + bb.w;
                }
            }
            uint2 u;
            u.x = pack_h2(__float2half_rn(v.x), __float2half_rn(v.y));
            u.y = pack_h2(__float2half_rn(v.z), __float2half_rn(v.w));
            *(uint2*)&Ash[r * ASTR + q * 4] = u;
        }
        // ---- stage B (64 x 64 fp32 -> fp16 hi/lo): 4 float4/thread ----
#pragma unroll
        for (int it = 0; it < 4; it++) {
            int idx = it * 256 + tid;
            int kk = idx >> 4, n4 = (idx & 15) * 4;
            float4 v = *(const float4*)(B + (size_t)(k0 + kk) * Ncol + n0 + n4);
            __half hx = __float2half_rn(v.x), hy = __float2half_rn(v.y);
            __half hz = __float2half_rn(v.z), hw = __float2half_rn(v.w);
            __half lx = __float2half_rn(v.x - __half2float(hx));
            __half ly = __float2half_rn(v.y - __half2float(hy));
            __half lz = __float2half_rn(v.z - __half2float(hz));
            __half lw = __float2half_rn(v.w - __half2float(hw));
            uint2 uh, ul;
            uh.x = pack_h2(hx, hy); uh.y = pack_h2(hz, hw);
            ul.x = pack_h2(lx, ly); ul.y = pack_h2(lz, lw);
            *(uint2*)&Bsh[kk * BSTR + n4] = uh;
            *(uint2*)&Bsl[kk * BSTR + n4] = ul;
        }
        __syncthreads();

        // ---- compute: 4 k16 steps ----
#pragma unroll
        for (int ks = 0; ks < 4; ks++) {
            uint32_t ah[2][4], bh[4][2], bl[4][2];
#pragma unroll
            for (int mi = 0; mi < 2; mi++)
                ldsm_x4(ah[mi], aOff[mi] + ks * 32);
#pragma unroll
            for (int ni = 0; ni < 4; ni++) {
                uint32_t bo = bOff + (ks * 16 * BSTR + ni * 8) * 2;
                ldsm_x2t(bh[ni], uBh + bo);
                ldsm_x2t(bl[ni], uBl + bo);
            }
#pragma unroll
            for (int mi = 0; mi < 2; mi++)
#pragma unroll
                for (int ni = 0; ni < 4; ni++) {
                    mma_f16(acc[mi][ni], ah[mi], bh[ni]);
                    mma_f16(acc[mi][ni], ah[mi], bl[ni]);
                }
        }
    }

    // ---- epilogue ----
    const int g = lane >> 2;
    const int tig = lane & 3;
#pragma unroll
    for (int mi = 0; mi < 2; mi++) {
        int row0 = m0 + wm * 32 + mi * 16 + g;
        int row1 = row0 + 8;
        float s0 = 1.f, s1 = 1.f;
        if (EPI == 0) {
            if (row0 < M) s0 = g_deg[row0];
            if (row1 < M) s1 = g_deg[row1];
        }
#pragma unroll
        for (int ni = 0; ni < 4; ni++) {
            int col = n0 + wn * 32 + ni * 8 + tig * 2;
            float v0 = acc[mi][ni][0], v1 = acc[mi][ni][1];
            float v2 = acc[mi][ni][2], v3 = acc[mi][ni][3];
            if (EPI == 0) {
                v0 *= s0; v1 *= s0; v2 *= s1; v3 *= s1;
            } else {
                float2 b = *(const float2*)(bias + col);
                v0 += b.x; v1 += b.y; v2 += b.x; v3 += b.y;
                if (EPI == 1) {
                    v0 = fmaxf(v0, 0.f); v1 = fmaxf(v1, 0.f);
                    v2 = fmaxf(v2, 0.f); v3 = fmaxf(v3, 0.f);
                }
            }
            if (row0 < M) {
                float* p = C0 + (size_t)row0 * Ncol + col;
                *(float2*)p = make_float2(v0, v1);
                if (EPI == 3) {
                    *(float2*)(p + (size_t)Nn * Cc) = make_float2(v0, v1);
                    *(float2*)(p + (size_t)2 * Nn * Cc) = make_float2(v0, v1);
                }
            }
            if (row1 < M) {
                float* p = C0 + (size_t)row1 * Ncol + col;
                *(float2*)p = make_float2(v2, v3);
                if (EPI == 3) {
                    *(float2*)(p + (size_t)Nn * Cc) = make_float2(v2, v3);
                    *(float2*)(p + (size_t)2 * Nn * Cc) = make_float2(v2, v3);
                }
            }
        }
    }
}

// ---------------------------------------------------------------------------
// CSR gather, 4-way unrolled: agg[d] = hprime[d] + sum hprime[src]
__global__ void gather_k() {
    int d = blockIdx.x * 8 + (threadIdx.x >> 5);
    int lane = threadIdx.x & 31;
    if (d >= Nn) return;
    const float4* hp = (const float4*)g_hprime;
    float4 a0 = hp[(size_t)d * 32 + lane];
    float4 a1 = make_float4(0.f, 0.f, 0.f, 0.f);
    float4 a2 = make_float4(0.f, 0.f, 0.f, 0.f);
    float4 a3 = make_float4(0.f, 0.f, 0.f, 0.f);
    int beg = g_rowptr[d] + g_bsum[d >> 9];
    int end = beg + g_cnt[d];
    int e = beg;
    for (; e + 3 < end; e += 4) {
        int s0 = g_esrc[e], s1 = g_esrc[e + 1], s2 = g_esrc[e + 2], s3 = g_esrc[e + 3];
        float4 v0 = hp[(size_t)s0 * 32 + lane];
        float4 v1 = hp[(size_t)s1 * 32 + lane];
        float4 v2 = hp[(size_t)s2 * 32 + lane];
        float4 v3 = hp[(size_t)s3 * 32 + lane];
        a0.x += v0.x; a0.y += v0.y; a0.z += v0.z; a0.w += v0.w;
        a1.x += v1.x; a1.y += v1.y; a1.z += v1.z; a1.w += v1.w;
        a2.x += v2.x; a2.y += v2.y; a2.z += v2.z; a2.w += v2.w;
        a3.x += v3.x; a3.y += v3.y; a3.z += v3.z; a3.w += v3.w;
    }
    for (; e < end; e++) {
        int s0 = g_esrc[e];
        float4 v0 = hp[(size_t)s0 * 32 + lane];
        a0.x += v0.x; a0.y += v0.y; a0.z += v0.z; a0.w += v0.w;
    }
    a0.x += a1.x + a2.x + a3.x;
    a0.y += a1.y + a2.y + a3.y;
    a0.z += a1.z + a2.z + a3.z;
    a0.w += a1.w + a2.w + a3.w;
    ((float4*)g_agg)[(size_t)d * 32 + lane] = a0;
}

// ---------------------------------------------------------------------------
// loss: logits already replicated by gemm3; read slice 0 only.
__global__ void loss_k(const int* __restrict__ label, const int* __restrict__ m0,
                       const int* __restrict__ m1, const int* __restrict__ m2,
                       const float* __restrict__ out) {
    __shared__ float sa[6];
    int tid = threadIdx.x;
    if (tid < 6) sa[tid] = 0.0f;
    __syncthreads();

    int r = blockIdx.x * 8 + (tid >> 5);
    int lane = tid & 31;
    if (r < Nn) {
        const float* row = out + (size_t)r * Cc;
        float x0 = row[lane];
        float x1 = row[lane + 32];

        float m = fmaxf(x0, x1);
#pragma unroll
        for (int off = 16; off >= 1; off >>= 1)
            m = fmaxf(m, __shfl_xor_sync(0xffffffffu, m, off));
        float se = expf(x0 - m) + expf(x1 - m);
#pragma unroll
        for (int off = 16; off >= 1; off >>= 1)
            se += __shfl_xor_sync(0xffffffffu, se, off);
        float lse = m + logf(se);
        int l = label[r];
        float cand = (l & 32) ? x1 : x0;
        float v = __shfl_sync(0xffffffffu, cand, l & 31);
        float loss = lse - v;
        if (lane == 0) {
            float t0 = (m0[r] == 1) ? 1.0f : 0.0f;
            float t1 = (m1[r] == 1) ? 1.0f : 0.0f;
            float t2 = (m2[r] == 1) ? 1.0f : 0.0f;
            atomicAdd(&sa[0], loss * t0);
            atomicAdd(&sa[1], loss * t1);
            atomicAdd(&sa[2], loss * t2);
            atomicAdd(&sa[3], t0);
            atomicAdd(&sa[4], t1);
            atomicAdd(&sa[5], t2);
        }
    }
    __syncthreads();
    if (tid < 6) atomicAdd(&g_acc[tid], sa[tid]);
}

__global__ void finalize_k(float* __restrict__ out) {
    int k = threadIdx.x;
    if (k < 3) out[(size_t)3 * Nn * Cc + k] = g_acc[k] / g_acc[3 + k];
}

// ---------------------------------------------------------------------------
extern "C" void kernel_launch(void* const* d_in, const int* in_sizes, int n_in,
                              void* d_out, int out_size) {
    const float* feature = (const float*)d_in[0];
    const int* adj       = (const int*)d_in[1];
    const int* label     = (const int*)d_in[2];
    const int* tmask     = (const int*)d_in[3];
    const int* dmask     = (const int*)d_in[4];
    const int* temask    = (const int*)d_in[5];
    const float* W_gcn   = (const float*)d_in[6];
    const float* b_gcn   = (const float*)d_in[7];
    const float* W_ff    = (const float*)d_in[8];
    const float* b_ff    = (const float*)d_in[9];
    const float* W_pred  = (const float*)d_in[10];
    const float* b_pred  = (const float*)d_in[11];
    float* out = (float*)d_out;

    float* d_hprime; cudaGetSymbolAddress((void**)&d_hprime, g_hprime);
    float* d_agg;    cudaGetSymbolAddress((void**)&d_agg, g_agg);
    float* d_hh;     cudaGetSymbolAddress((void**)&d_hh, g_hh);

    const int MB = (Nn + 127) / 128;  // 391

    // 1. CSR build + dinv (scan2 fused into scan1 last block)
    init_k<<<(Nn + 255) / 256, 256>>>();
    cnt_k<<<(Ee + 255) / 256, 256>>>(adj);
    scan1_k<<<NBLK, SCAN_B>>>();
    fill_k<<<(Ee + 255) / 256, 256>>>(adj);

    // 2. hprime = dinv * (feature @ W_gcn)
    {
        dim3 grid(MB, Ff / 64);
        mmagemm<128, 0, 0><<<grid, 256>>>(feature, W_gcn, nullptr, nullptr,
                                          d_hprime, Nn, Ff);
    }

    // 3. agg[d] = hprime[d] + sum_{s->d} hprime[s]
    gather_k<<<(Nn + 7) / 8, 256>>>();

    // 4+5. hh = relu((dinv*agg + b_gcn) @ W_ff + b_ff)
    {
        dim3 grid(MB, Hh / 64);
        mmagemm<128, 1, 1><<<grid, 256>>>(d_agg, W_ff, b_gcn, b_ff,
                                          d_hh, Nn, Hh);
    }

    // 6. logits = hh @ W_pred + b_pred -> all 3 output slices
    {
        dim3 grid(MB, Cc / 64);
        mmagemm<256, 0, 3><<<grid, 256>>>(d_hh, W_pred, nullptr, b_pred,
                                          out, Nn, Cc);
    }

    // 7. loss + masked sums
    loss_k<<<(Nn + 7) / 8, 256>>>(label, tmask, dmask, temask, out);

    // 8. scalars
    finalize_k<<<1, 32>>>(out);
}

// round 11
// speedup vs baseline: 1.1389x; 1.1389x over previous
#include <cuda_runtime.h>
#include <cuda_fp16.h>
#include <cstdint>

// Problem constants
constexpr int Nn = 50000;
constexpr int Ee = 800000;
constexpr int Ff = 128;
constexpr int Hh = 256;
constexpr int Cc = 64;

constexpr int SCAN_B = 512;
constexpr int NBLK = (Nn + SCAN_B - 1) / SCAN_B;  // 98

// Scratch (fp16 activations)
__device__ __half g_hprime[(size_t)Nn * Ff];
__device__ __half g_agg[(size_t)Nn * Ff];
__device__ __half g_hh[(size_t)Nn * Hh];
__device__ float g_deg[Nn];     // dinv
__device__ float g_acc[8];
__device__ int g_cnt[Nn];
__device__ int g_fill[Nn];
__device__ int g_rowptr[Nn];    // block-local exclusive scan (+ g_bsum[i>>9])
__device__ int g_bsum[128];
__device__ int g_esrc[Ee];

// ---------------------------------------------------------------------------
__global__ void init_k() {
    int i = blockIdx.x * blockDim.x + threadIdx.x;
    if (i < Nn) { g_cnt[i] = 0; g_fill[i] = 0; }
    if (i < 8) g_acc[i] = 0.0f;
}
__global__ void cnt_k(const int* __restrict__ adj) {
    int e = blockIdx.x * blockDim.x + threadIdx.x;
    if (e < Ee) atomicAdd(&g_cnt[adj[Ee + e]], 1);
}
__global__ void scan1_k() {
    __shared__ int s[SCAN_B];
    int tid = threadIdx.x;
    int i = blockIdx.x * SCAN_B + tid;
    int v = (i < Nn) ? g_cnt[i] : 0;
    s[tid] = v;
    __syncthreads();
#pragma unroll
    for (int off = 1; off < SCAN_B; off <<= 1) {
        int t = (tid >= off) ? s[tid - off] : 0;
        __syncthreads();
        s[tid] += t;
        __syncthreads();
    }
    if (i < Nn) {
        g_rowptr[i] = s[tid] - v;
        g_deg[i] = rsqrtf((float)(v + 1));
    }
    if (tid == SCAN_B - 1) g_bsum[blockIdx.x] = s[tid];
}
__global__ void scan2_k() {
    __shared__ int ws[4];
    int tid = threadIdx.x;  // 128
    int v = (tid < NBLK) ? g_bsum[tid] : 0;
    int x = v;
#pragma unroll
    for (int o = 1; o < 32; o <<= 1) {
        int t = __shfl_up_sync(0xffffffffu, x, o);
        if ((tid & 31) >= o) x += t;
    }
    if ((tid & 31) == 31) ws[tid >> 5] = x;
    __syncthreads();
    if (tid == 0) {
        int run = 0;
#pragma unroll
        for (int i = 0; i < 4; i++) { int t = ws[i]; ws[i] = run; run += t; }
    }
    __syncthreads();
    if (tid < NBLK) g_bsum[tid] = x - v + ws[tid >> 5];
}
__global__ void fill_k(const int* __restrict__ adj) {
    int e = blockIdx.x * blockDim.x + threadIdx.x;
    if (e >= Ee) return;
    int src = adj[e];
    int dst = adj[Ee + e];
    int pos = g_rowptr[dst] + g_bsum[dst >> 9] + atomicAdd(&g_fill[dst], 1);
    g_esrc[pos] = src;
}

// ---------------------------------------------------------------------------
__device__ __forceinline__ uint32_t smem_u32(const void* p) {
    uint32_t a;
    asm("{ .reg .u64 t; cvta.to.shared.u64 t, %1; cvt.u32.u64 %0, t; }"
        : "=r"(a) : "l"(p));
    return a;
}
__device__ __forceinline__ void ldsm_x4(uint32_t* r, uint32_t addr) {
    asm volatile("ldmatrix.sync.aligned.m8n8.x4.shared.b16 {%0,%1,%2,%3}, [%4];"
                 : "=r"(r[0]), "=r"(r[1]), "=r"(r[2]), "=r"(r[3]) : "r"(addr));
}
__device__ __forceinline__ void ldsm_x2t(uint32_t* r, uint32_t addr) {
    asm volatile("ldmatrix.sync.aligned.m8n8.x2.trans.shared.b16 {%0,%1}, [%2];"
                 : "=r"(r[0]), "=r"(r[1]) : "r"(addr));
}
__device__ __forceinline__ void mma_f16(float* d, const uint32_t* a, const uint32_t* b) {
    asm volatile(
        "mma.sync.aligned.m16n8k16.row.col.f32.f16.f16.f32 "
        "{%0,%1,%2,%3}, {%4,%5,%6,%7}, {%8,%9}, {%0,%1,%2,%3};"
        : "+f"(d[0]), "+f"(d[1]), "+f"(d[2]), "+f"(d[3])
        : "r"(a[0]), "r"(a[1]), "r"(a[2]), "r"(a[3]), "r"(b[0]), "r"(b[1]));
}
__device__ __forceinline__ uint32_t pack_h2(__half a, __half b) {
    __half2 h = __halves2half2(a, b);
    return *(uint32_t*)&h;
}
__device__ __forceinline__ float4 h4_to_f4(uint2 u) {
    float2 fa = __half22float2(*(__half2*)&u.x);
    float2 fb = __half22float2(*(__half2*)&u.y);
    return make_float4(fa.x, fa.y, fb.x, fb.y);
}
__device__ __forceinline__ uint2 f4_to_h4(float4 v) {
    __half2 a = __floats2half2_rn(v.x, v.y);
    __half2 b = __floats2half2_rn(v.z, v.w);
    uint2 u;
    u.x = *(uint32_t*)&a;
    u.y = *(uint32_t*)&b;
    return u;
}

// ---------------------------------------------------------------------------
// fp16 2-term HMMA GEMM: C = A@B via Ah*(Bh+Bl); A single fp16, B split hi/lo.
// BM=128, BN=64, BK=32, 256 threads, 8 warps (4m x 2n), warp tile 32x32.
// AHALF: 0 -> A fp32 ; 1 -> A fp16 (activations)
// AXF:   1 -> A'[r][k] = dinv[r]*A[r][k] + abias[k]
// EPI:   0 -> v*=dinv[r] -> half C0
//        1 -> relu(v+bias) -> half C0
//        3 -> v+bias -> fp32 C0, replicated to 3 slices
template <int K, int AHALF, int AXF, int EPI>
__global__ void __launch_bounds__(256)
mmagemm(const void* __restrict__ Ap, const float* __restrict__ B,
        const float* __restrict__ abias, const float* __restrict__ bias,
        void* __restrict__ C0p, int M, int Ncol) {
    constexpr int ASTR = 40;   // fp16 elems per A smem row (80B)
    constexpr int BSTR = 72;   // fp16 elems per B smem row (144B)
    __shared__ __align__(16) __half Ash[128 * ASTR];
    __shared__ __align__(16) __half Bsh[32 * BSTR];
    __shared__ __align__(16) __half Bsl[32 * BSTR];

    const int tid = threadIdx.x;
    const int wid = tid >> 5;
    const int lane = tid & 31;
    const int wm = wid & 3;
    const int wn = wid >> 2;
    const int m0 = blockIdx.x * 128;
    const int n0 = blockIdx.y * 64;

    const uint32_t uAs = smem_u32(Ash);
    const uint32_t uBh = smem_u32(Bsh);
    const uint32_t uBl = smem_u32(Bsl);

    const int l15 = lane & 15;
    const int lh = lane >> 4;
    uint32_t aOff[2];
#pragma unroll
    for (int mi = 0; mi < 2; mi++)
        aOff[mi] = uAs + (uint32_t)((wm * 32 + mi * 16 + l15) * (ASTR * 2) + lh * 16);
    const uint32_t bOff = (uint32_t)(l15 * (BSTR * 2) + wn * 64);

    float acc[2][4][4];
#pragma unroll
    for (int mi = 0; mi < 2; mi++)
#pragma unroll
        for (int ni = 0; ni < 4; ni++)
#pragma unroll
            for (int j = 0; j < 4; j++) acc[mi][ni][j] = 0.0f;

    constexpr int NC = K / 32;
#pragma unroll 1
    for (int c = 0; c < NC; c++) {
        const int k0 = c * 32;
        if (c > 0) __syncthreads();
        // ---- stage A (128 x 32 -> fp16 smem) ----
        if (AHALF == 0) {
            const float* A = (const float*)Ap;
#pragma unroll
            for (int it = 0; it < 4; it++) {
                int idx = it * 256 + tid;
                int r = idx >> 3, q = idx & 7;
                int gr = m0 + r;
                float4 v = make_float4(0.f, 0.f, 0.f, 0.f);
                if (gr < M) {
                    v = *(const float4*)(A + (size_t)gr * K + k0 + q * 4);
                    if (AXF) {
                        float sc = g_deg[gr];
                        float4 bb = *(const float4*)(abias + k0 + q * 4);
                        v.x = sc * v.x + bb.x; v.y = sc * v.y + bb.y;
                        v.z = sc * v.z + bb.z; v.w = sc * v.w + bb.w;
                    }
                }
                uint2 u;
                u.x = pack_h2(__float2half_rn(v.x), __float2half_rn(v.y));
                u.y = pack_h2(__float2half_rn(v.z), __float2half_rn(v.w));
                *(uint2*)&Ash[r * ASTR + q * 4] = u;
            }
        } else {
            const __half* A = (const __half*)Ap;
            // 128 rows x 32 halfs = 512 uint4 slots (8 halfs each)
#pragma unroll
            for (int it = 0; it < 2; it++) {
                int idx = it * 256 + tid;
                int r = idx >> 2, q = idx & 3;
                int gr = m0 + r;
                uint4 u = make_uint4(0, 0, 0, 0);
                if (gr < M) {
                    u = *(const uint4*)(A + (size_t)gr * K + k0 + q * 8);
                    if (AXF) {
                        float sc = g_deg[gr];
                        float4 b0 = *(const float4*)(abias + k0 + q * 8);
                        float4 b1 = *(const float4*)(abias + k0 + q * 8 + 4);
                        float4 f0 = h4_to_f4(make_uint2(u.x, u.y));
                        float4 f1 = h4_to_f4(make_uint2(u.z, u.w));
                        f0.x = sc * f0.x + b0.x; f0.y = sc * f0.y + b0.y;
                        f0.z = sc * f0.z + b0.z; f0.w = sc * f0.w + b0.w;
                        f1.x = sc * f1.x + b1.x; f1.y = sc * f1.y + b1.y;
                        f1.z = sc * f1.z + b1.z; f1.w = sc * f1.w + b1.w;
                        uint2 p0 = f4_to_h4(f0), p1 = f4_to_h4(f1);
                        u = make_uint4(p0.x, p0.y, p1.x, p1.y);
                    }
                }
                *(uint4*)&Ash[r * ASTR + q * 8] = u;
            }
        }
        // ---- stage B (32 x 64 fp32 -> fp16 hi/lo) ----
#pragma unroll
        for (int it = 0; it < 2; it++) {
            int idx = it * 256 + tid;
            int kk = idx >> 4, n4 = (idx & 15) * 4;
            float4 v = *(const float4*)(B + (size_t)(k0 + kk) * Ncol + n0 + n4);
            __half hx = __float2half_rn(v.x), hy = __float2half_rn(v.y);
            __half hz = __float2half_rn(v.z), hw = __float2half_rn(v.w);
            __half lx = __float2half_rn(v.x - __half2float(hx));
            __half ly = __float2half_rn(v.y - __half2float(hy));
            __half lz = __float2half_rn(v.z - __half2float(hz));
            __half lw = __float2half_rn(v.w - __half2float(hw));
            uint2 uh, ul;
            uh.x = pack_h2(hx, hy); uh.y = pack_h2(hz, hw);
            ul.x = pack_h2(lx, ly); ul.y = pack_h2(lz, lw);
            *(uint2*)&Bsh[kk * BSTR + n4] = uh;
            *(uint2*)&Bsl[kk * BSTR + n4] = ul;
        }
        __syncthreads();

        // ---- compute: 2 k16 steps ----
#pragma unroll
        for (int ks = 0; ks < 2; ks++) {
            uint32_t ah[2][4], bh[4][2], bl[4][2];
#pragma unroll
            for (int mi = 0; mi < 2; mi++)
                ldsm_x4(ah[mi], aOff[mi] + ks * 32);
#pragma unroll
            for (int ni = 0; ni < 4; ni++) {
                uint32_t bo = bOff + ks * 16 * (BSTR * 2) + ni * 16;
                ldsm_x2t(bh[ni], uBh + bo);
                ldsm_x2t(bl[ni], uBl + bo);
            }
#pragma unroll
            for (int mi = 0; mi < 2; mi++)
#pragma unroll
                for (int ni = 0; ni < 4; ni++) {
                    mma_f16(acc[mi][ni], ah[mi], bh[ni]);
                    mma_f16(acc[mi][ni], ah[mi], bl[ni]);
                }
        }
    }

    // ---- epilogue ----
    const int g = lane >> 2;
    const int tig = lane & 3;
#pragma unroll
    for (int mi = 0; mi < 2; mi++) {
        int row0 = m0 + wm * 32 + mi * 16 + g;
        int row1 = row0 + 8;
        float s0 = 1.f, s1 = 1.f;
        if (EPI == 0) {
            if (row0 < M) s0 = g_deg[row0];
            if (row1 < M) s1 = g_deg[row1];
        }
#pragma unroll
        for (int ni = 0; ni < 4; ni++) {
            int col = n0 + wn * 32 + ni * 8 + tig * 2;
            float v0 = acc[mi][ni][0], v1 = acc[mi][ni][1];
            float v2 = acc[mi][ni][2], v3 = acc[mi][ni][3];
            if (EPI == 0) {
                v0 *= s0; v1 *= s0; v2 *= s1; v3 *= s1;
            } else {
                float2 b = *(const float2*)(bias + col);
                v0 += b.x; v1 += b.y; v2 += b.x; v3 += b.y;
                if (EPI == 1) {
                    v0 = fmaxf(v0, 0.f); v1 = fmaxf(v1, 0.f);
                    v2 = fmaxf(v2, 0.f); v3 = fmaxf(v3, 0.f);
                }
            }
            if (EPI == 0 || EPI == 1) {
                __half* C = (__half*)C0p;
                if (row0 < M)
                    *(__half2*)(C + (size_t)row0 * Ncol + col) = __floats2half2_rn(v0, v1);
                if (row1 < M)
                    *(__half2*)(C + (size_t)row1 * Ncol + col) = __floats2half2_rn(v2, v3);
            } else {
                float* C = (float*)C0p;
                if (row0 < M) {
                    float* p = C + (size_t)row0 * Ncol + col;
                    *(float2*)p = make_float2(v0, v1);
                    *(float2*)(p + (size_t)Nn * Cc) = make_float2(v0, v1);
                    *(float2*)(p + (size_t)2 * Nn * Cc) = make_float2(v0, v1);
                }
                if (row1 < M) {
                    float* p = C + (size_t)row1 * Ncol + col;
                    *(float2*)p = make_float2(v2, v3);
                    *(float2*)(p + (size_t)Nn * Cc) = make_float2(v2, v3);
                    *(float2*)(p + (size_t)2 * Nn * Cc) = make_float2(v2, v3);
                }
            }
        }
    }
}

// ---------------------------------------------------------------------------
// CSR gather on fp16 rows, fp32 accumulation, 4-way unrolled.
// agg[d] = hprime[d] + sum hprime[src]; one warp per dst, uint2 (4 halfs)/lane.
__global__ void gather_k() {
    int d = blockIdx.x * 8 + (threadIdx.x >> 5);
    int lane = threadIdx.x & 31;
    if (d >= Nn) return;
    const uint2* hp = (const uint2*)g_hprime;
    float4 a0 = h4_to_f4(hp[(size_t)d * 32 + lane]);
    float4 a1 = make_float4(0.f, 0.f, 0.f, 0.f);
    float4 a2 = make_float4(0.f, 0.f, 0.f, 0.f);
    float4 a3 = make_float4(0.f, 0.f, 0.f, 0.f);
    int beg = g_rowptr[d] + g_bsum[d >> 9];
    int end = beg + g_cnt[d];
    int e = beg;
    for (; e + 3 < end; e += 4) {
        int s0 = g_esrc[e], s1 = g_esrc[e + 1], s2 = g_esrc[e + 2], s3 = g_esrc[e + 3];
        float4 v0 = h4_to_f4(hp[(size_t)s0 * 32 + lane]);
        float4 v1 = h4_to_f4(hp[(size_t)s1 * 32 + lane]);
        float4 v2 = h4_to_f4(hp[(size_t)s2 * 32 + lane]);
        float4 v3 = h4_to_f4(hp[(size_t)s3 * 32 + lane]);
        a0.x += v0.x; a0.y += v0.y; a0.z += v0.z; a0.w += v0.w;
        a1.x += v1.x; a1.y += v1.y; a1.z += v1.z; a1.w += v1.w;
        a2.x += v2.x; a2.y += v2.y; a2.z += v2.z; a2.w += v2.w;
        a3.x += v3.x; a3.y += v3.y; a3.z += v3.z; a3.w += v3.w;
    }
    for (; e < end; e++) {
        float4 v0 = h4_to_f4(hp[(size_t)g_esrc[e] * 32 + lane]);
        a0.x += v0.x; a0.y += v0.y; a0.z += v0.z; a0.w += v0.w;
    }
    a0.x += a1.x + a2.x + a3.x;
    a0.y += a1.y + a2.y + a3.y;
    a0.z += a1.z + a2.z + a3.z;
    a0.w += a1.w + a2.w + a3.w;
    ((uint2*)g_agg)[(size_t)d * 32 + lane] = f4_to_h4(a0);
}

// ---------------------------------------------------------------------------
// loss: logits already replicated by gemm3; read slice 0 only.
__global__ void loss_k(const int* __restrict__ label, const int* __restrict__ m0,
                       const int* __restrict__ m1, const int* __restrict__ m2,
                       const float* __restrict__ out) {
    __shared__ float sa[6];
    int tid = threadIdx.x;
    if (tid < 6) sa[tid] = 0.0f;
    __syncthreads();

    int r = blockIdx.x * 8 + (tid >> 5);
    int lane = tid & 31;
    if (r < Nn) {
        const float* row = out + (size_t)r * Cc;
        float x0 = row[lane];
        float x1 = row[lane + 32];

        float m = fmaxf(x0, x1);
#pragma unroll
        for (int off = 16; off >= 1; off >>= 1)
            m = fmaxf(m, __shfl_xor_sync(0xffffffffu, m, off));
        float se = expf(x0 - m) + expf(x1 - m);
#pragma unroll
        for (int off = 16; off >= 1; off >>= 1)
            se += __shfl_xor_sync(0xffffffffu, se, off);
        float lse = m + logf(se);
        int l = label[r];
        float cand = (l & 32) ? x1 : x0;
        float v = __shfl_sync(0xffffffffu, cand, l & 31);
        float loss = lse - v;
        if (lane == 0) {
            float t0 = (m0[r] == 1) ? 1.0f : 0.0f;
            float t1 = (m1[r] == 1) ? 1.0f : 0.0f;
            float t2 = (m2[r] == 1) ? 1.0f : 0.0f;
            atomicAdd(&sa[0], loss * t0);
            atomicAdd(&sa[1], loss * t1);
            atomicAdd(&sa[2], loss * t2);
            atomicAdd(&sa[3], t0);
            atomicAdd(&sa[4], t1);
            atomicAdd(&sa[5], t2);
        }
    }
    __syncthreads();
    if (tid < 6) atomicAdd(&g_acc[tid], sa[tid]);
}

__global__ void finalize_k(float* __restrict__ out) {
    int k = threadIdx.x;
    if (k < 3) out[(size_t)3 * Nn * Cc + k] = g_acc[k] / g_acc[3 + k];
}

// ---------------------------------------------------------------------------
extern "C" void kernel_launch(void* const* d_in, const int* in_sizes, int n_in,
                              void* d_out, int out_size) {
    const float* feature = (const float*)d_in[0];
    const int* adj       = (const int*)d_in[1];
    const int* label     = (const int*)d_in[2];
    const int* tmask     = (const int*)d_in[3];
    const int* dmask     = (const int*)d_in[4];
    const int* temask    = (const int*)d_in[5];
    const float* W_gcn   = (const float*)d_in[6];
    const float* b_gcn   = (const float*)d_in[7];
    const float* W_ff    = (const float*)d_in[8];
    const float* b_ff    = (const float*)d_in[9];
    const float* W_pred  = (const float*)d_in[10];
    const float* b_pred  = (const float*)d_in[11];
    float* out = (float*)d_out;

    void* d_hprime; cudaGetSymbolAddress(&d_hprime, g_hprime);
    void* d_agg;    cudaGetSymbolAddress(&d_agg, g_agg);
    void* d_hh;     cudaGetSymbolAddress(&d_hh, g_hh);

    const int MB = (Nn + 127) / 128;  // 391

    // 1. CSR build + dinv
    init_k<<<(Nn + 255) / 256, 256>>>();
    cnt_k<<<(Ee + 255) / 256, 256>>>(adj);
    scan1_k<<<NBLK, SCAN_B>>>();
    scan2_k<<<1, 128>>>();
    fill_k<<<(Ee + 255) / 256, 256>>>(adj);

    // 2. hprime = dinv * (feature @ W_gcn)  [fp16 out]
    {
        dim3 grid(MB, Ff / 64);
        mmagemm<128, 0, 0, 0><<<grid, 256>>>(feature, W_gcn, nullptr, nullptr,
                                             d_hprime, Nn, Ff);
    }

    // 3. agg[d] = hprime[d] + sum_{s->d} hprime[s]   [fp16 in/out, fp32 acc]
    gather_k<<<(Nn + 7) / 8, 256>>>();

    // 4+5. hh = relu((dinv*agg + b_gcn) @ W_ff + b_ff)  [fp16 A, fp16 out]
    {
        dim3 grid(MB, Hh / 64);
        mmagemm<128, 1, 1, 1><<<grid, 256>>>(d_agg, W_ff, b_gcn, b_ff,
                                             d_hh, Nn, Hh);
    }

    // 6. logits = hh @ W_pred + b_pred -> all 3 output slices  [fp16 A, fp32 out]
    {
        dim3 grid(MB, Cc / 64);
        mmagemm<256, 1, 0, 3><<<grid, 256>>>(d_hh, W_pred, nullptr, b_pred,
                                             out, Nn, Cc);
    }

    // 7. loss + masked sums
    loss_k<<<(Nn + 7) / 8, 256>>>(label, tmask, dmask, temask, out);

    // 8. scalars
    finalize_k<<<1, 32>>>(out);
}

// round 13
// speedup vs baseline: 1.1676x; 1.0252x over previous
#include <cuda_runtime.h>
#include <cuda_fp16.h>
#include <cstdint>

// Problem constants
constexpr int Nn = 50000;
constexpr int Ee = 800000;
constexpr int Ff = 128;
constexpr int Hh = 256;
constexpr int Cc = 64;

constexpr int SCAN_B = 512;
constexpr int NBLK = (Nn + SCAN_B - 1) / SCAN_B;  // 98

// Scratch (fp16 activations)
__device__ __half g_hprime[(size_t)Nn * Ff];   // feature @ W_gcn (unscaled)
__device__ __half g_agg[(size_t)Nn * Ff];
__device__ __half g_hh[(size_t)Nn * Hh];
__device__ float g_deg[Nn];     // dinv
__device__ float g_acc[8];
__device__ int g_cnt[Nn];
__device__ int g_rowptr[Nn];    // block-local scan; post-fill = local row END
__device__ int g_bsum[128];
__device__ int g_esrc[Ee];

// ---------------------------------------------------------------------------
__global__ void init_k() {
    int i = blockIdx.x * blockDim.x + threadIdx.x;
    if (i < Nn) g_cnt[i] = 0;
    if (i < 8) g_acc[i] = 0.0f;
}
__global__ void cnt_k(const int* __restrict__ adj) {
    int e = blockIdx.x * blockDim.x + threadIdx.x;
    if (e < Ee) atomicAdd(&g_cnt[adj[Ee + e]], 1);
}
__global__ void scan1_k() {
    __shared__ int s[SCAN_B];
    int tid = threadIdx.x;
    int i = blockIdx.x * SCAN_B + tid;
    int v = (i < Nn) ? g_cnt[i] : 0;
    s[tid] = v;
    __syncthreads();
#pragma unroll
    for (int off = 1; off < SCAN_B; off <<= 1) {
        int t = (tid >= off) ? s[tid - off] : 0;
        __syncthreads();
        s[tid] += t;
        __syncthreads();
    }
    if (i < Nn) {
        g_rowptr[i] = s[tid] - v;
        g_deg[i] = rsqrtf((float)(v + 1));
    }
    if (tid == SCAN_B - 1) g_bsum[blockIdx.x] = s[tid];
}
__global__ void scan2_k() {
    __shared__ int ws[4];
    int tid = threadIdx.x;  // 128
    int v = (tid < NBLK) ? g_bsum[tid] : 0;
    int x = v;
#pragma unroll
    for (int o = 1; o < 32; o <<= 1) {
        int t = __shfl_up_sync(0xffffffffu, x, o);
        if ((tid & 31) >= o) x += t;
    }
    if ((tid & 31) == 31) ws[tid >> 5] = x;
    __syncthreads();
    if (tid == 0) {
        int run = 0;
#pragma unroll
        for (int i = 0; i < 4; i++) { int t = ws[i]; ws[i] = run; run += t; }
    }
    __syncthreads();
    if (tid < NBLK) g_bsum[tid] = x - v + ws[tid >> 5];
}
// fill: rowptr doubles as cursor; 2 edges/thread
__global__ void fill_k(const int* __restrict__ adj) {
    int t = blockIdx.x * blockDim.x + threadIdx.x;
    constexpr int HALF = Ee / 2;
    if (t >= HALF) return;
#pragma unroll
    for (int h = 0; h < 2; h++) {
        int e = t + h * HALF;
        int src = adj[e];
        int dst = adj[Ee + e];
        int pos = atomicAdd(&g_rowptr[dst], 1) + g_bsum[dst >> 9];
        g_esrc[pos] = src;
    }
}

// ---------------------------------------------------------------------------
__device__ __forceinline__ uint32_t smem_u32(const void* p) {
    uint32_t a;
    asm("{ .reg .u64 t; cvta.to.shared.u64 t, %1; cvt.u32.u64 %0, t; }"
        : "=r"(a) : "l"(p));
    return a;
}
__device__ __forceinline__ void ldsm_x4(uint32_t* r, uint32_t addr) {
    asm volatile("ldmatrix.sync.aligned.m8n8.x4.shared.b16 {%0,%1,%2,%3}, [%4];"
                 : "=r"(r[0]), "=r"(r[1]), "=r"(r[2]), "=r"(r[3]) : "r"(addr));
}
__device__ __forceinline__ void ldsm_x2t(uint32_t* r, uint32_t addr) {
    asm volatile("ldmatrix.sync.aligned.m8n8.x2.trans.shared.b16 {%0,%1}, [%2];"
                 : "=r"(r[0]), "=r"(r[1]) : "r"(addr));
}
__device__ __forceinline__ void mma_f16(float* d, const uint32_t* a, const uint32_t* b) {
    asm volatile(
        "mma.sync.aligned.m16n8k16.row.col.f32.f16.f16.f32 "
        "{%0,%1,%2,%3}, {%4,%5,%6,%7}, {%8,%9}, {%0,%1,%2,%3};"
        : "+f"(d[0]), "+f"(d[1]), "+f"(d[2]), "+f"(d[3])
        : "r"(a[0]), "r"(a[1]), "r"(a[2]), "r"(a[3]), "r"(b[0]), "r"(b[1]));
}
__device__ __forceinline__ uint32_t pack_h2(__half a, __half b) {
    __half2 h = __halves2half2(a, b);
    return *(uint32_t*)&h;
}
__device__ __forceinline__ float4 h4_to_f4(uint2 u) {
    float2 fa = __half22float2(*(__half2*)&u.x);
    float2 fb = __half22float2(*(__half2*)&u.y);
    return make_float4(fa.x, fa.y, fb.x, fb.y);
}
__device__ __forceinline__ uint2 f4_to_h4(float4 v) {
    __half2 a = __floats2half2_rn(v.x, v.y);
    __half2 b = __floats2half2_rn(v.z, v.w);
    uint2 u;
    u.x = *(uint32_t*)&a;
    u.y = *(uint32_t*)&b;
    return u;
}

// ---------------------------------------------------------------------------
// fp16 2-term HMMA GEMM: C = A@B via Ah*(Bh+Bl); A single fp16, B split hi/lo.
// BM=128, BN=64, BK=32, 256 threads, 8 warps (4m x 2n), warp tile 32x32.
// AHALF: 0 -> A fp32 ; 1 -> A fp16
// AXF:   1 -> A'[r][k] = dinv[r]*A[r][k] + abias[k]
// EPI:   1 -> relu(v+bias) -> half C0
//        2 -> plain v -> half C0 (no dinv; no bias)
//        3 -> v+bias -> fp32 C0 replicated to 3 slices
template <int K, int AHALF, int AXF, int EPI>
__global__ void __launch_bounds__(256)
mmagemm(const void* __restrict__ Ap, const float* __restrict__ B,
        const float* __restrict__ abias, const float* __restrict__ bias,
        void* __restrict__ C0p, int M, int Ncol) {
    constexpr int ASTR = 40;
    constexpr int BSTR = 72;
    __shared__ __align__(16) __half Ash[128 * ASTR];
    __shared__ __align__(16) __half Bsh[32 * BSTR];
    __shared__ __align__(16) __half Bsl[32 * BSTR];

    const int tid = threadIdx.x;
    const int wid = tid >> 5;
    const int lane = tid & 31;
    const int wm = wid & 3;
    const int wn = wid >> 2;
    const int m0 = blockIdx.x * 128;
    const int n0 = blockIdx.y * 64;

    const uint32_t uAs = smem_u32(Ash);
    const uint32_t uBh = smem_u32(Bsh);
    const uint32_t uBl = smem_u32(Bsl);

    const int l15 = lane & 15;
    const int lh = lane >> 4;
    uint32_t aOff[2];
#pragma unroll
    for (int mi = 0; mi < 2; mi++)
        aOff[mi] = uAs + (uint32_t)((wm * 32 + mi * 16 + l15) * (ASTR * 2) + lh * 16);
    const uint32_t bOff = (uint32_t)(l15 * (BSTR * 2) + wn * 64);

    float acc[2][4][4];
#pragma unroll
    for (int mi = 0; mi < 2; mi++)
#pragma unroll
        for (int ni = 0; ni < 4; ni++)
#pragma unroll
            for (int j = 0; j < 4; j++) acc[mi][ni][j] = 0.0f;

    constexpr int NC = K / 32;
#pragma unroll 1
    for (int c = 0; c < NC; c++) {
        const int k0 = c * 32;
        if (c > 0) __syncthreads();
        if (AHALF == 0) {
            const float* A = (const float*)Ap;
#pragma unroll
            for (int it = 0; it < 4; it++) {
                int idx = it * 256 + tid;
                int r = idx >> 3, q = idx & 7;
                int gr = m0 + r;
                float4 v = make_float4(0.f, 0.f, 0.f, 0.f);
                if (gr < M) {
                    v = *(const float4*)(A + (size_t)gr * K + k0 + q * 4);
                    if (AXF) {
                        float sc = g_deg[gr];
                        float4 bb = *(const float4*)(abias + k0 + q * 4);
                        v.x = sc * v.x + bb.x; v.y = sc * v.y + bb.y;
                        v.z = sc * v.z + bb.z; v.w = sc * v.w + bb.w;
                    }
                }
                uint2 u;
                u.x = pack_h2(__float2half_rn(v.x), __float2half_rn(v.y));
                u.y = pack_h2(__float2half_rn(v.z), __float2half_rn(v.w));
                *(uint2*)&Ash[r * ASTR + q * 4] = u;
            }
        } else {
            const __half* A = (const __half*)Ap;
#pragma unroll
            for (int it = 0; it < 2; it++) {
                int idx = it * 256 + tid;
                int r = idx >> 2, q = idx & 3;
                int gr = m0 + r;
                uint4 u = make_uint4(0, 0, 0, 0);
                if (gr < M) {
                    u = *(const uint4*)(A + (size_t)gr * K + k0 + q * 8);
                    if (AXF) {
                        float sc = g_deg[gr];
                        float4 b0 = *(const float4*)(abias + k0 + q * 8);
                        float4 b1 = *(const float4*)(abias + k0 + q * 8 + 4);
                        float4 f0 = h4_to_f4(make_uint2(u.x, u.y));
                        float4 f1 = h4_to_f4(make_uint2(u.z, u.w));
                        f0.x = sc * f0.x + b0.x; f0.y = sc * f0.y + b0.y;
                        f0.z = sc * f0.z + b0.z; f0.w = sc * f0.w + b0.w;
                        f1.x = sc * f1.x + b1.x; f1.y = sc * f1.y + b1.y;
                        f1.z = sc * f1.z + b1.z; f1.w = sc * f1.w + b1.w;
                        uint2 p0 = f4_to_h4(f0), p1 = f4_to_h4(f1);
                        u = make_uint4(p0.x, p0.y, p1.x, p1.y);
                    }
                }
                *(uint4*)&Ash[r * ASTR + q * 8] = u;
            }
        }
#pragma unroll
        for (int it = 0; it < 2; it++) {
            int idx = it * 256 + tid;
            int kk = idx >> 4, n4 = (idx & 15) * 4;
            float4 v = *(const float4*)(B + (size_t)(k0 + kk) * Ncol + n0 + n4);
            __half hx = __float2half_rn(v.x), hy = __float2half_rn(v.y);
            __half hz = __float2half_rn(v.z), hw = __float2half_rn(v.w);
            __half lx = __float2half_rn(v.x - __half2float(hx));
            __half ly = __float2half_rn(v.y - __half2float(hy));
            __half lz = __float2half_rn(v.z - __half2float(hz));
            __half lw = __float2half_rn(v.w - __half2float(hw));
            uint2 uh, ul;
            uh.x = pack_h2(hx, hy); uh.y = pack_h2(hz, hw);
            ul.x = pack_h2(lx, ly); ul.y = pack_h2(lz, lw);
            *(uint2*)&Bsh[kk * BSTR + n4] = uh;
            *(uint2*)&Bsl[kk * BSTR + n4] = ul;
        }
        __syncthreads();

#pragma unroll
        for (int ks = 0; ks < 2; ks++) {
            uint32_t ah[2][4], bh[4][2], bl[4][2];
#pragma unroll
            for (int mi = 0; mi < 2; mi++)
                ldsm_x4(ah[mi], aOff[mi] + ks * 32);
#pragma unroll
            for (int ni = 0; ni < 4; ni++) {
                uint32_t bo = bOff + ks * 16 * (BSTR * 2) + ni * 16;
                ldsm_x2t(bh[ni], uBh + bo);
                ldsm_x2t(bl[ni], uBl + bo);
            }
#pragma unroll
            for (int mi = 0; mi < 2; mi++)
#pragma unroll
                for (int ni = 0; ni < 4; ni++) {
                    mma_f16(acc[mi][ni], ah[mi], bh[ni]);
                    mma_f16(acc[mi][ni], ah[mi], bl[ni]);
                }
        }
    }

    const int g = lane >> 2;
    const int tig = lane & 3;
#pragma unroll
    for (int mi = 0; mi < 2; mi++) {
        int row0 = m0 + wm * 32 + mi * 16 + g;
        int row1 = row0 + 8;
#pragma unroll
        for (int ni = 0; ni < 4; ni++) {
            int col = n0 + wn * 32 + ni * 8 + tig * 2;
            float v0 = acc[mi][ni][0], v1 = acc[mi][ni][1];
            float v2 = acc[mi][ni][2], v3 = acc[mi][ni][3];
            if (EPI == 1 || EPI == 3) {
                float2 b = *(const float2*)(bias + col);
                v0 += b.x; v1 += b.y; v2 += b.x; v3 += b.y;
                if (EPI == 1) {
                    v0 = fmaxf(v0, 0.f); v1 = fmaxf(v1, 0.f);
                    v2 = fmaxf(v2, 0.f); v3 = fmaxf(v3, 0.f);
                }
            }
            if (EPI == 1 || EPI == 2) {
                __half* C = (__half*)C0p;
                if (row0 < M)
                    *(__half2*)(C + (size_t)row0 * Ncol + col) = __floats2half2_rn(v0, v1);
                if (row1 < M)
                    *(__half2*)(C + (size_t)row1 * Ncol + col) = __floats2half2_rn(v2, v3);
            } else {
                float* C = (float*)C0p;
                if (row0 < M) {
                    float* p = C + (size_t)row0 * Ncol + col;
                    *(float2*)p = make_float2(v0, v1);
                    *(float2*)(p + (size_t)Nn * Cc) = make_float2(v0, v1);
                    *(float2*)(p + (size_t)2 * Nn * Cc) = make_float2(v0, v1);
                }
                if (row1 < M) {
                    float* p = C + (size_t)row1 * Ncol + col;
                    *(float2*)p = make_float2(v2, v3);
                    *(float2*)(p + (size_t)Nn * Cc) = make_float2(v2, v3);
                    *(float2*)(p + (size_t)2 * Nn * Cc) = make_float2(v2, v3);
                }
            }
        }
    }
}

// ---------------------------------------------------------------------------
// CSR gather with per-source dinv scaling (hprime is UNSCALED here):
// agg[d] = dinv[d]*hprime[d] + sum_s dinv[s]*hprime[s]
__global__ void gather_k() {
    int d = blockIdx.x * 8 + (threadIdx.x >> 5);
    int lane = threadIdx.x & 31;
    if (d >= Nn) return;
    const uint2* hp = (const uint2*)g_hprime;
    float sd = g_deg[d];
    float4 self = h4_to_f4(hp[(size_t)d * 32 + lane]);
    float4 a0, a1, a2, a3;
    a0.x = sd * self.x; a0.y = sd * self.y; a0.z = sd * self.z; a0.w = sd * self.w;
    a1 = make_float4(0.f, 0.f, 0.f, 0.f);
    a2 = make_float4(0.f, 0.f, 0.f, 0.f);
    a3 = make_float4(0.f, 0.f, 0.f, 0.f);
    int base = g_bsum[d >> 9];
    int end = g_rowptr[d] + base;    // cursor ended at row end
    int beg = end - g_cnt[d];
    int e = beg;
    for (; e + 3 < end; e += 4) {
        int s0 = g_esrc[e], s1 = g_esrc[e + 1], s2 = g_esrc[e + 2], s3 = g_esrc[e + 3];
        float c0 = g_deg[s0], c1 = g_deg[s1], c2 = g_deg[s2], c3 = g_deg[s3];
        float4 v0 = h4_to_f4(hp[(size_t)s0 * 32 + lane]);
        float4 v1 = h4_to_f4(hp[(size_t)s1 * 32 + lane]);
        float4 v2 = h4_to_f4(hp[(size_t)s2 * 32 + lane]);
        float4 v3 = h4_to_f4(hp[(size_t)s3 * 32 + lane]);
        a0.x += c0 * v0.x; a0.y += c0 * v0.y; a0.z += c0 * v0.z; a0.w += c0 * v0.w;
        a1.x += c1 * v1.x; a1.y += c1 * v1.y; a1.z += c1 * v1.z; a1.w += c1 * v1.w;
        a2.x += c2 * v2.x; a2.y += c2 * v2.y; a2.z += c2 * v2.z; a2.w += c2 * v2.w;
        a3.x += c3 * v3.x; a3.y += c3 * v3.y; a3.z += c3 * v3.z; a3.w += c3 * v3.w;
    }
    for (; e < end; e++) {
        int s0 = g_esrc[e];
        float c0 = g_deg[s0];
        float4 v0 = h4_to_f4(hp[(size_t)s0 * 32 + lane]);
        a0.x += c0 * v0.x; a0.y += c0 * v0.y; a0.z += c0 * v0.z; a0.w += c0 * v0.w;
    }
    a0.x += a1.x + a2.x + a3.x;
    a0.y += a1.y + a2.y + a3.y;
    a0.z += a1.z + a2.z + a3.z;
    a0.w += a1.w + a2.w + a3.w;
    ((uint2*)g_agg)[(size_t)d * 32 + lane] = f4_to_h4(a0);
}

// ---------------------------------------------------------------------------
__global__ void loss_k(const int* __restrict__ label, const int* __restrict__ m0,
                       const int* __restrict__ m1, const int* __restrict__ m2,
                       const float* __restrict__ out) {
    __shared__ float sa[6];
    int tid = threadIdx.x;
    if (tid < 6) sa[tid] = 0.0f;
    __syncthreads();

    int r = blockIdx.x * 8 + (tid >> 5);
    int lane = tid & 31;
    if (r < Nn) {
        const float* row = out + (size_t)r * Cc;
        float x0 = row[lane];
        float x1 = row[lane + 32];

        float m = fmaxf(x0, x1);
#pragma unroll
        for (int off = 16; off >= 1; off >>= 1)
            m = fmaxf(m, __shfl_xor_sync(0xffffffffu, m, off));
        float se = expf(x0 - m) + expf(x1 - m);
#pragma unroll
        for (int off = 16; off >= 1; off >>= 1)
            se += __shfl_xor_sync(0xffffffffu, se, off);
        float lse = m + logf(se);
        int l = label[r];
        float cand = (l & 32) ? x1 : x0;
        float v = __shfl_sync(0xffffffffu, cand, l & 31);
        float loss = lse - v;
        if (lane == 0) {
            float t0 = (m0[r] == 1) ? 1.0f : 0.0f;
            float t1 = (m1[r] == 1) ? 1.0f : 0.0f;
            float t2 = (m2[r] == 1) ? 1.0f : 0.0f;
            atomicAdd(&sa[0], loss * t0);
            atomicAdd(&sa[1], loss * t1);
            atomicAdd(&sa[2], loss * t2);
            atomicAdd(&sa[3], t0);
            atomicAdd(&sa[4], t1);
            atomicAdd(&sa[5], t2);
        }
    }
    __syncthreads();
    if (tid < 6) atomicAdd(&g_acc[tid], sa[tid]);
}

__global__ void finalize_k(float* __restrict__ out) {
    int k = threadIdx.x;
    if (k < 3) out[(size_t)3 * Nn * Cc + k] = g_acc[k] / g_acc[3 + k];
}

// ---------------------------------------------------------------------------
extern "C" void kernel_launch(void* const* d_in, const int* in_sizes, int n_in,
                              void* d_out, int out_size) {
    const float* feature = (const float*)d_in[0];
    const int* adj       = (const int*)d_in[1];
    const int* label     = (const int*)d_in[2];
    const int* tmask     = (const int*)d_in[3];
    const int* dmask     = (const int*)d_in[4];
    const int* temask    = (const int*)d_in[5];
    const float* W_gcn   = (const float*)d_in[6];
    const float* b_gcn   = (const float*)d_in[7];
    const float* W_ff    = (const float*)d_in[8];
    const float* b_ff    = (const float*)d_in[9];
    const float* W_pred  = (const float*)d_in[10];
    const float* b_pred  = (const float*)d_in[11];
    float* out = (float*)d_out;

    void* d_hprime; cudaGetSymbolAddress(&d_hprime, g_hprime);
    void* d_agg;    cudaGetSymbolAddress(&d_agg, g_agg);
    void* d_hh;     cudaGetSymbolAddress(&d_hh, g_hh);

    const int MB = (Nn + 127) / 128;  // 391

    // side stream + events (created once on the eager correctness call)
    static cudaStream_t s2 = nullptr;
    static cudaEvent_t evFork = nullptr, evJoin = nullptr;
    if (!s2) {
        cudaStreamCreateWithFlags(&s2, cudaStreamNonBlocking);
        cudaEventCreateWithFlags(&evFork, cudaEventDisableTiming);
        cudaEventCreateWithFlags(&evJoin, cudaEventDisableTiming);
    }

    // fork: CSR build + dinv on s2, gemm1 (independent) on main stream
    cudaEventRecord(evFork, 0);
    cudaStreamWaitEvent(s2, evFork, 0);

    init_k<<<(Nn + 255) / 256, 256, 0, s2>>>();
    cnt_k<<<(Ee + 255) / 256, 256, 0, s2>>>(adj);
    scan1_k<<<NBLK, SCAN_B, 0, s2>>>();
    scan2_k<<<1, 128, 0, s2>>>();
    fill_k<<<(Ee / 2 + 255) / 256, 256, 0, s2>>>(adj);

    // gemm1: hprime = feature @ W_gcn (UNscaled; dinv applied in gather)
    {
        dim3 grid(MB, Ff / 64);
        mmagemm<128, 0, 0, 2><<<grid, 256>>>(feature, W_gcn, nullptr, nullptr,
                                             d_hprime, Nn, Ff);
    }

    // join: gather needs CSR+dinv (s2) and hprime (main)
    cudaEventRecord(evJoin, s2);
    cudaStreamWaitEvent(0, evJoin, 0);

    // agg[d] = dinv[d]*hprime[d] + sum dinv[s]*hprime[s]
    gather_k<<<(Nn + 7) / 8, 256>>>();

    // hh = relu((dinv*agg + b_gcn) @ W_ff + b_ff)
    {
        dim3 grid(MB, Hh / 64);
        mmagemm<128, 1, 1, 1><<<grid, 256>>>(d_agg, W_ff, b_gcn, b_ff,
                                             d_hh, Nn, Hh);
    }
    // logits -> 3 slices
    {
        dim3 grid(MB, Cc / 64);
        mmagemm<256, 1, 0, 3><<<grid, 256>>>(d_hh, W_pred, nullptr, b_pred,
                                             out, Nn, Cc);
    }

    loss_k<<<(Nn + 7) / 8, 256>>>(label, tmask, dmask, temask, out);
    finalize_k<<<1, 32>>>(out);
}